// round 7
// baseline (speedup 1.0000x reference)
#include <cuda_runtime.h>
#include <cuda_fp16.h>
#include <cstdint>

#define MAXN 100000
#define MAXE 3200000
#define HID 64
#define EPSV 1e-5f

// ---------------- device scratch (zero-initialized at module load) -----------
__device__ __align__(128) float        g_dinv[MAXN];
__device__ __align__(128) unsigned int g_t16[MAXN * 32];    // u as half2 (64 half / row)
__device__ __align__(128) float        g_agg[MAXN * HID];   // aggregated pre-BN features
__device__ __align__(128) int          g_adj[MAXE];         // CSR column (src) indices
__device__ __align__(128) int          g_cnt[MAXN];         // zeroed by classifier epilogue
__device__ __align__(128) int          g_rowptr[MAXN + 1];
__device__ __align__(128) int          g_cursor[MAXN];
__device__ float g_sum3[3 * HID];     // per-layer BN sums (zeroed in k_cnt)
__device__ float g_sumsq3[3 * HID];

// ---------------- dtype detect: warp-uniform ballot on first 32 odd words -----
__device__ __forceinline__ bool detect_is64(const unsigned int* raw) {
    unsigned v = raw[2 * (threadIdx.x & 31) + 1];
    return __ballot_sync(0xffffffffu, v != 0u) == 0u;
}

// ---------------- #1 count in-degree (+ zero BN stat slots) -------------------
__global__ void k_cnt(const void* __restrict__ ei, long long E) {
    bool is64 = detect_is64((const unsigned int*)ei);
    if (blockIdx.x == 0 && threadIdx.x < 3 * HID) {
        g_sum3[threadIdx.x] = 0.f; g_sumsq3[threadIdx.x] = 0.f;
    }
    long long e = (long long)blockIdx.x * blockDim.x + threadIdx.x;
    if (e >= E) return;
    int d = is64 ? (int)((const long long*)ei)[E + e] : ((const int*)ei)[E + e];
    atomicAdd(&g_cnt[d], 1);
}

// ---------------- #2 single-block full exclusive scan (coalesced tiles) -------
// One block of 1024 threads walks N in 1024-wide tiles, carrying the running
// total. Writes rowptr (exclusive), cursor, dinv.
__global__ void k_scan_one(int N, int E) {
    __shared__ int wsum[32];
    int tid = threadIdx.x;
    int lane = tid & 31, warp = tid >> 5;
    int carry = 0;
    int tiles = (N + 1023) >> 10;
    for (int t = 0; t < tiles; t++) {
        int i = (t << 10) + tid;
        int c = (i < N) ? g_cnt[i] : 0;
        int x = c;
#pragma unroll
        for (int o = 1; o < 32; o <<= 1) {
            int y = __shfl_up_sync(0xffffffffu, x, o);
            if (lane >= o) x += y;
        }
        if (lane == 31) wsum[warp] = x;
        __syncthreads();
        if (tid < 32) {
            int w = wsum[tid];
#pragma unroll
            for (int o = 1; o < 32; o <<= 1) {
                int y = __shfl_up_sync(0xffffffffu, w, o);
                if (tid >= o) w += y;
            }
            wsum[tid] = w;
        }
        __syncthreads();
        int base = (warp > 0 ? wsum[warp - 1] : 0) + carry;
        if (i < N) {
            int excl = base + x - c;
            g_rowptr[i] = excl;
            g_cursor[i] = excl;
            g_dinv[i] = rsqrtf((float)c + 1.0f);
        }
        carry += wsum[31];
        __syncthreads();   // protect wsum reads from next tile's writes
    }
    if (tid == 0) g_rowptr[N] = E;
}

// ---------------- fp16 repack+store of u = a * dinv ---------------------------
__device__ __forceinline__ void store_u16(int n, int lane, float a0, float a1) {
    float dv = g_dinv[n];
    a0 *= dv; a1 *= dv;
    int idx0 = (2 * lane) & 31;
    float lo_a0 = __shfl_sync(0xffffffffu, a0, idx0);
    float hi_a0 = __shfl_sync(0xffffffffu, a0, idx0 + 1);
    float lo_a1 = __shfl_sync(0xffffffffu, a1, idx0);
    float hi_a1 = __shfl_sync(0xffffffffu, a1, idx0 + 1);
    float lo = lane < 16 ? lo_a0 : lo_a1;
    float hi = lane < 16 ? hi_a0 : hi_a1;
    __half2 hp = __floats2half2_rn(lo, hi);
    g_t16[n * 32 + lane] = *(unsigned int*)&hp;
}

// ---------------- #3 heterogeneous grid: CSR fill blocks + layer0 blocks ------
// Fill is atomic/latency bound (issue ~8%), layer0 is FFMA bound; interleaving
// roles (every 3rd block = layer0) co-schedules them on the same SMs.
__global__ void k_fill_layer0(const void* __restrict__ ei, long long E,
                              const float* __restrict__ x,
                              const float* __restrict__ Win,
                              const float* __restrict__ bin,
                              const float* __restrict__ Wg,
                              int N, int eB, int gB) {
    __shared__ float Ws[HID * HID];
    __shared__ float Wi[12 * HID];
    __shared__ float bs[HID];

    int bid = blockIdx.x;
    int k = bid / 3, m = bid - k * 3;

    if (m == 2) {
        // ---- layer0 role: u = (relu(x@Win+bin) @ Wg0) * dinv, 2 nodes/warp ----
        if (k >= gB) return;
        for (int i = threadIdx.x; i < HID * HID; i += blockDim.x) Ws[i] = Wg[i];
        for (int i = threadIdx.x; i < 12 * HID; i += blockDim.x) Wi[i] = Win[i];
        if (threadIdx.x < HID) bs[threadIdx.x] = bin[threadIdx.x];
        __syncthreads();
        int lane = threadIdx.x & 31, warp = threadIdx.x >> 5;
        int nA = (k * 8 + warp) * 2;
        int nB = nA + 1;
        if (nA >= N) return;
        bool hasB = nB < N;
        float xvA = lane < 12 ? x[nA * 12 + lane] : 0.f;
        float xvB = (hasB && lane < 12) ? x[nB * 12 + lane] : 0.f;
        float vloA = bs[lane], vhiA = bs[lane + 32];
        float vloB = vloA,     vhiB = vhiA;
#pragma unroll
        for (int c = 0; c < 12; c++) {
            float wlo = Wi[c * HID + lane], whi = Wi[c * HID + lane + 32];
            float xA = __shfl_sync(0xffffffffu, xvA, c);
            float xB = __shfl_sync(0xffffffffu, xvB, c);
            vloA = fmaf(xA, wlo, vloA); vhiA = fmaf(xA, whi, vhiA);
            vloB = fmaf(xB, wlo, vloB); vhiB = fmaf(xB, whi, vhiB);
        }
        vloA = fmaxf(vloA, 0.f); vhiA = fmaxf(vhiA, 0.f);
        vloB = fmaxf(vloB, 0.f); vhiB = fmaxf(vhiB, 0.f);
        float a0A = 0.f, a1A = 0.f, a0B = 0.f, a1B = 0.f;
#pragma unroll
        for (int c = 0; c < 32; c++) {
            float wlo = Ws[c * HID + lane], whi = Ws[c * HID + lane + 32];
            float xA = __shfl_sync(0xffffffffu, vloA, c);
            float xB = __shfl_sync(0xffffffffu, vloB, c);
            a0A = fmaf(xA, wlo, a0A); a1A = fmaf(xA, whi, a1A);
            a0B = fmaf(xB, wlo, a0B); a1B = fmaf(xB, whi, a1B);
        }
#pragma unroll
        for (int c = 0; c < 32; c++) {
            float wlo = Ws[(c + 32) * HID + lane], whi = Ws[(c + 32) * HID + lane + 32];
            float xA = __shfl_sync(0xffffffffu, vhiA, c);
            float xB = __shfl_sync(0xffffffffu, vhiB, c);
            a0A = fmaf(xA, wlo, a0A); a1A = fmaf(xA, whi, a1A);
            a0B = fmaf(xB, wlo, a0B); a1B = fmaf(xB, whi, a1B);
        }
        store_u16(nA, lane, a0A, a1A);
        if (hasB) store_u16(nB, lane, a0B, a1B);
        return;
    }

    // ---- fill role: scatter src into CSR slot -------------------------------
    int fid = 2 * k + m;
    if (fid >= eB) return;
    bool is64 = detect_is64((const unsigned int*)ei);
    long long e = (long long)fid * blockDim.x + threadIdx.x;
    if (e >= E) return;
    int s, d;
    if (is64) {
        const long long* p = (const long long*)ei;
        s = (int)p[e]; d = (int)p[E + e];
    } else {
        const int* p = (const int*)ei;
        s = p[e]; d = p[E + e];
    }
    int pos = atomicAdd(&g_cursor[d], 1);
    g_adj[pos] = s;
}

// ---------------- layers 1,2: u = (relu(BN(agg)) @ Wg) * dinv -----------------
__global__ void k_gemm64(const float* __restrict__ Wg, const float* __restrict__ gamma,
                         const float* __restrict__ beta, int slot, int N) {
    __shared__ float Ws[HID * HID];
    for (int i = threadIdx.x; i < HID * HID; i += blockDim.x) Ws[i] = Wg[i];
    __syncthreads();
    int lane = threadIdx.x & 31, warp = threadIdx.x >> 5;
    float inv = 1.0f / (float)N;
    int c0 = lane, c1 = lane + 32;
    float mu0 = g_sum3[slot * HID + c0] * inv;
    float mu1 = g_sum3[slot * HID + c1] * inv;
    float v0 = g_sumsq3[slot * HID + c0] * inv - mu0 * mu0;
    float v1 = g_sumsq3[slot * HID + c1] * inv - mu1 * mu1;
    float sc0 = gamma[c0] * rsqrtf(v0 + EPSV);
    float sc1 = gamma[c1] * rsqrtf(v1 + EPSV);
    float sh0 = fmaf(-mu0, sc0, beta[c0]);
    float sh1 = fmaf(-mu1, sc1, beta[c1]);

    int nA = (blockIdx.x * (blockDim.x >> 5) + warp) * 2;
    int nB = nA + 1;
    if (nA >= N) return;
    bool hasB = nB < N;
    float vloA = fmaxf(fmaf(g_agg[nA * HID + c0], sc0, sh0), 0.f);
    float vhiA = fmaxf(fmaf(g_agg[nA * HID + c1], sc1, sh1), 0.f);
    float vloB = 0.f, vhiB = 0.f;
    if (hasB) {
        vloB = fmaxf(fmaf(g_agg[nB * HID + c0], sc0, sh0), 0.f);
        vhiB = fmaxf(fmaf(g_agg[nB * HID + c1], sc1, sh1), 0.f);
    }
    float a0A = 0.f, a1A = 0.f, a0B = 0.f, a1B = 0.f;
#pragma unroll
    for (int c = 0; c < 32; c++) {
        float wlo = Ws[c * HID + lane], whi = Ws[c * HID + lane + 32];
        float xA = __shfl_sync(0xffffffffu, vloA, c);
        float xB = __shfl_sync(0xffffffffu, vloB, c);
        a0A = fmaf(xA, wlo, a0A); a1A = fmaf(xA, whi, a1A);
        a0B = fmaf(xB, wlo, a0B); a1B = fmaf(xB, whi, a1B);
    }
#pragma unroll
    for (int c = 0; c < 32; c++) {
        float wlo = Ws[(c + 32) * HID + lane], whi = Ws[(c + 32) * HID + lane + 32];
        float xA = __shfl_sync(0xffffffffu, vhiA, c);
        float xB = __shfl_sync(0xffffffffu, vhiB, c);
        a0A = fmaf(xA, wlo, a0A); a1A = fmaf(xA, whi, a1A);
        a0B = fmaf(xB, wlo, a0B); a1B = fmaf(xB, whi, a1B);
    }
    store_u16(nA, lane, a0A, a1A);
    if (hasB) store_u16(nB, lane, a0B, a1B);
}

// ---------------- CSR gather + fused BN stats (launch #4 -> profiled) ---------
__global__ void k_agg(const float* __restrict__ bg, int slot, int N) {
    __shared__ float ss[HID], sq[HID];
    if (threadIdx.x < HID) { ss[threadIdx.x] = 0.f; sq[threadIdx.x] = 0.f; }
    __syncthreads();

    int lane = threadIdx.x & 31;
    int half = lane >> 4;
    int hl   = lane & 15;
    int warp_g = (int)((blockIdx.x * blockDim.x + threadIdx.x) >> 5);
    int nwarps = (int)((gridDim.x * blockDim.x) >> 5);

    const uint2* __restrict__ u2 = (const uint2*)g_t16;
    float4 bvec = ((const float4*)bg)[hl];

    float4 s1 = {0.f, 0.f, 0.f, 0.f};
    float4 s2 = {0.f, 0.f, 0.f, 0.f};

    for (int n = warp_g; n < N; n += nwarps) {
        int beg = g_rowptr[n], end = g_rowptr[n + 1];
        float dv = g_dinv[n];
        float4 acc = {0.f, 0.f, 0.f, 0.f};
        if (half == 0) {
            uint2 sv = u2[n * 16 + hl];
            float2 f0 = __half22float2(*(__half2*)&sv.x);
            float2 f1 = __half22float2(*(__half2*)&sv.y);
            acc.x = f0.x; acc.y = f0.y; acc.z = f1.x; acc.w = f1.y;
        }

        int i = beg + half;
        for (; i + 14 < end; i += 16) {
            int e0 = g_adj[i],      e1 = g_adj[i + 2];
            int e2 = g_adj[i + 4],  e3 = g_adj[i + 6];
            int e4 = g_adj[i + 8],  e5 = g_adj[i + 10];
            int e6 = g_adj[i + 12], e7 = g_adj[i + 14];
            uint2 v0 = u2[e0 * 16 + hl], v1 = u2[e1 * 16 + hl];
            uint2 v2 = u2[e2 * 16 + hl], v3 = u2[e3 * 16 + hl];
            uint2 v4 = u2[e4 * 16 + hl], v5 = u2[e5 * 16 + hl];
            uint2 v6 = u2[e6 * 16 + hl], v7 = u2[e7 * 16 + hl];
            float2 a00 = __half22float2(*(__half2*)&v0.x), a01 = __half22float2(*(__half2*)&v0.y);
            float2 a10 = __half22float2(*(__half2*)&v1.x), a11 = __half22float2(*(__half2*)&v1.y);
            float2 a20 = __half22float2(*(__half2*)&v2.x), a21 = __half22float2(*(__half2*)&v2.y);
            float2 a30 = __half22float2(*(__half2*)&v3.x), a31 = __half22float2(*(__half2*)&v3.y);
            float2 a40 = __half22float2(*(__half2*)&v4.x), a41 = __half22float2(*(__half2*)&v4.y);
            float2 a50 = __half22float2(*(__half2*)&v5.x), a51 = __half22float2(*(__half2*)&v5.y);
            float2 a60 = __half22float2(*(__half2*)&v6.x), a61 = __half22float2(*(__half2*)&v6.y);
            float2 a70 = __half22float2(*(__half2*)&v7.x), a71 = __half22float2(*(__half2*)&v7.y);
            acc.x += ((a00.x + a10.x) + (a20.x + a30.x)) + ((a40.x + a50.x) + (a60.x + a70.x));
            acc.y += ((a00.y + a10.y) + (a20.y + a30.y)) + ((a40.y + a50.y) + (a60.y + a70.y));
            acc.z += ((a01.x + a11.x) + (a21.x + a31.x)) + ((a41.x + a51.x) + (a61.x + a71.x));
            acc.w += ((a01.y + a11.y) + (a21.y + a31.y)) + ((a41.y + a51.y) + (a61.y + a71.y));
        }
        for (; i + 6 < end; i += 8) {
            int e0 = g_adj[i],     e1 = g_adj[i + 2];
            int e2 = g_adj[i + 4], e3 = g_adj[i + 6];
            uint2 v0 = u2[e0 * 16 + hl], v1 = u2[e1 * 16 + hl];
            uint2 v2 = u2[e2 * 16 + hl], v3 = u2[e3 * 16 + hl];
            float2 a00 = __half22float2(*(__half2*)&v0.x), a01 = __half22float2(*(__half2*)&v0.y);
            float2 a10 = __half22float2(*(__half2*)&v1.x), a11 = __half22float2(*(__half2*)&v1.y);
            float2 a20 = __half22float2(*(__half2*)&v2.x), a21 = __half22float2(*(__half2*)&v2.y);
            float2 a30 = __half22float2(*(__half2*)&v3.x), a31 = __half22float2(*(__half2*)&v3.y);
            acc.x += (a00.x + a10.x) + (a20.x + a30.x);
            acc.y += (a00.y + a10.y) + (a20.y + a30.y);
            acc.z += (a01.x + a11.x) + (a21.x + a31.x);
            acc.w += (a01.y + a11.y) + (a21.y + a31.y);
        }
        for (; i < end; i += 2) {
            int s = g_adj[i];
            uint2 v = u2[s * 16 + hl];
            float2 f0 = __half22float2(*(__half2*)&v.x);
            float2 f1 = __half22float2(*(__half2*)&v.y);
            acc.x += f0.x; acc.y += f0.y; acc.z += f1.x; acc.w += f1.y;
        }
        acc.x += __shfl_xor_sync(0xffffffffu, acc.x, 16);
        acc.y += __shfl_xor_sync(0xffffffffu, acc.y, 16);
        acc.z += __shfl_xor_sync(0xffffffffu, acc.z, 16);
        acc.w += __shfl_xor_sync(0xffffffffu, acc.w, 16);

        if (half == 0) {
            float4 o;
            o.x = fmaf(acc.x, dv, bvec.x);
            o.y = fmaf(acc.y, dv, bvec.y);
            o.z = fmaf(acc.z, dv, bvec.z);
            o.w = fmaf(acc.w, dv, bvec.w);
            ((float4*)g_agg)[(long long)n * 16 + hl] = o;
            s1.x += o.x; s1.y += o.y; s1.z += o.z; s1.w += o.w;
            s2.x = fmaf(o.x, o.x, s2.x); s2.y = fmaf(o.y, o.y, s2.y);
            s2.z = fmaf(o.z, o.z, s2.z); s2.w = fmaf(o.w, o.w, s2.w);
        }
    }

    if (half == 0) {
        atomicAdd(&ss[4 * hl + 0], s1.x); atomicAdd(&ss[4 * hl + 1], s1.y);
        atomicAdd(&ss[4 * hl + 2], s1.z); atomicAdd(&ss[4 * hl + 3], s1.w);
        atomicAdd(&sq[4 * hl + 0], s2.x); atomicAdd(&sq[4 * hl + 1], s2.y);
        atomicAdd(&sq[4 * hl + 2], s2.z); atomicAdd(&sq[4 * hl + 3], s2.w);
    }
    __syncthreads();
    if (threadIdx.x < HID) {
        atomicAdd(&g_sum3[slot * HID + threadIdx.x],   ss[threadIdx.x]);
        atomicAdd(&g_sumsq3[slot * HID + threadIdx.x], sq[threadIdx.x]);
    }
}

// ---------------- classifier + cleanup (re-zero g_cnt for next replay) -------
__global__ void k_classifier(const float* __restrict__ Wc1, const float* __restrict__ bc1,
                             const float* __restrict__ Wc2, const float* __restrict__ bc2,
                             const float* __restrict__ gamma, const float* __restrict__ beta,
                             float* __restrict__ out, int N) {
    int gid = blockIdx.x * blockDim.x + threadIdx.x;
    if (gid < N) g_cnt[gid] = 0;   // cleanup for next graph replay

    __shared__ float W1[64 * 32];
    __shared__ float W2[64];
    __shared__ float b1s[32];
    __shared__ float b2s[2];
    for (int i = threadIdx.x; i < 64 * 32; i += blockDim.x) W1[i] = Wc1[i];
    if (threadIdx.x < 64) W2[threadIdx.x] = Wc2[threadIdx.x];
    if (threadIdx.x < 32) b1s[threadIdx.x] = bc1[threadIdx.x];
    if (threadIdx.x < 2)  b2s[threadIdx.x] = bc2[threadIdx.x];
    __syncthreads();
    int lane = threadIdx.x & 31, warp = threadIdx.x >> 5;
    int n = blockIdx.x * (blockDim.x >> 5) + warp;
    if (n >= N) return;
    float inv = 1.0f / (float)N;
    int c0 = lane, c1 = lane + 32;
    float mu0 = g_sum3[2 * HID + c0] * inv;
    float mu1 = g_sum3[2 * HID + c1] * inv;
    float v0 = g_sumsq3[2 * HID + c0] * inv - mu0 * mu0;
    float v1 = g_sumsq3[2 * HID + c1] * inv - mu1 * mu1;
    float sc0 = gamma[c0] * rsqrtf(v0 + EPSV);
    float sc1 = gamma[c1] * rsqrtf(v1 + EPSV);
    float sh0 = fmaf(-mu0, sc0, beta[c0]);
    float sh1 = fmaf(-mu1, sc1, beta[c1]);

    float vlo = fmaf(g_agg[n * HID + c0], sc0, sh0);
    float vhi = fmaf(g_agg[n * HID + c1], sc1, sh1);
    float u = b1s[lane];
#pragma unroll
    for (int c = 0; c < 32; c++) {
        float xc = __shfl_sync(0xffffffffu, vlo, c);
        u = fmaf(xc, W1[c * 32 + lane], u);
    }
#pragma unroll
    for (int c = 0; c < 32; c++) {
        float xc = __shfl_sync(0xffffffffu, vhi, c);
        u = fmaf(xc, W1[(c + 32) * 32 + lane], u);
    }
    u = fmaxf(u, 0.f);
    float p0 = u * W2[lane * 2], p1 = u * W2[lane * 2 + 1];
#pragma unroll
    for (int o = 16; o > 0; o >>= 1) {
        p0 += __shfl_xor_sync(0xffffffffu, p0, o);
        p1 += __shfl_xor_sync(0xffffffffu, p1, o);
    }
    if (lane == 0) {
        out[n * 2]     = p0 + b2s[0];
        out[n * 2 + 1] = p1 + b2s[1];
    }
}

// ---------------- launch ------------------------------------------------------
extern "C" void kernel_launch(void* const* d_in, const int* in_sizes, int n_in,
                              void* d_out, int out_size) {
    const float* x    = (const float*)d_in[0];
    const void*  ei   = d_in[1];
    const float* W_in = (const float*)d_in[2];
    const float* b_in = (const float*)d_in[3];
    const float* W_g  = (const float*)d_in[4];
    const float* b_g  = (const float*)d_in[5];
    const float* gam  = (const float*)d_in[6];
    const float* bet  = (const float*)d_in[7];
    const float* W_c1 = (const float*)d_in[8];
    const float* b_c1 = (const float*)d_in[9];
    const float* W_c2 = (const float*)d_in[10];
    const float* b_c2 = (const float*)d_in[11];
    float* out = (float*)d_out;

    int N = in_sizes[0] / 12;
    long long E = (long long)in_sizes[1] / 2;

    const int TB = 256;
    int eB = (int)((E + TB - 1) / TB);          // fill blocks
    int gB = (N + 15) / 16;                     // layer0 blocks (2 nodes/warp)
    int half_e = (eB + 1) / 2;
    unsigned hetero = 3u * (unsigned)(half_e > gB ? half_e : gB);

    k_cnt<<<(unsigned)eB, TB>>>(ei, E);                              // #1
    k_scan_one<<<1, 1024>>>(N, (int)E);                              // #2
    k_fill_layer0<<<hetero, TB>>>(ei, E, x, W_in, b_in, W_g,
                                  N, eB, gB);                        // #3
    k_agg<<<2048, 256>>>(b_g, 0, N);                                 // #4 <- profiled
    for (int l = 1; l < 3; l++) {
        k_gemm64<<<(unsigned)gB, 256>>>(W_g + (long long)l * HID * HID,
                                        gam + (l - 1) * HID, bet + (l - 1) * HID,
                                        l - 1, N);
        k_agg<<<2048, 256>>>(b_g + l * HID, l, N);
    }
    k_classifier<<<(unsigned)((N + 7) / 8), 256>>>(W_c1, b_c1, W_c2, b_c2,
                                                   gam + 2 * HID, bet + 2 * HID,
                                                   out, N);
}

// round 8
// speedup vs baseline: 1.8182x; 1.8182x over previous
#include <cuda_runtime.h>
#include <cstdint>

#define MAXN 100000
#define MAXE 3200000
#define HID 64
#define EPSV 1e-5f

// ---------------- device scratch (zero-initialized at module load) -----------
__device__ __align__(128) float g_dinv[MAXN];
__device__ __align__(128) float g_t[MAXN * HID];      // u = (act @ W) * dinv, fp32
__device__ __align__(128) float g_agg[MAXN * HID];    // aggregated pre-BN features
__device__ __align__(128) int   g_adj[MAXE];          // CSR column (src) indices
__device__ __align__(128) int   g_cnt[MAXN];          // zeroed by classifier epilogue
__device__ __align__(128) int   g_rowptr[MAXN + 1];
__device__ __align__(128) int   g_cursor[MAXN];
__device__ __align__(128) int   g_bsum[1024];
__device__ float g_sum3[3 * HID];     // per-layer BN sums (zeroed in k_cnt)
__device__ float g_sumsq3[3 * HID];

// ---------------- dtype detect: warp-uniform ballot on first 32 odd words -----
__device__ __forceinline__ bool detect_is64(const unsigned int* raw) {
    unsigned v = raw[2 * (threadIdx.x & 31) + 1];
    return __ballot_sync(0xffffffffu, v != 0u) == 0u;
}

// ---------------- #1 count in-degree (+ zero BN stat slots) -------------------
__global__ void k_cnt(const void* __restrict__ ei, long long E) {
    bool is64 = detect_is64((const unsigned int*)ei);
    if (blockIdx.x == 0 && threadIdx.x < 3 * HID) {
        g_sum3[threadIdx.x] = 0.f; g_sumsq3[threadIdx.x] = 0.f;
    }
    long long e = (long long)blockIdx.x * blockDim.x + threadIdx.x;
    if (e >= E) return;
    int d = is64 ? (int)((const long long*)ei)[E + e] : ((const int*)ei)[E + e];
    atomicAdd(&g_cnt[d], 1);
}

// ---------------- #2 scan level 1: per-1024-block exclusive scan --------------
__global__ void k_scan1(int N) {
    __shared__ int wsum[32];
    int i = blockIdx.x * 1024 + threadIdx.x;
    int lane = threadIdx.x & 31, warp = threadIdx.x >> 5;
    int c = (i < N) ? g_cnt[i] : 0;
    int x = c;
#pragma unroll
    for (int o = 1; o < 32; o <<= 1) {
        int y = __shfl_up_sync(0xffffffffu, x, o);
        if (lane >= o) x += y;
    }
    if (lane == 31) wsum[warp] = x;
    __syncthreads();
    if (threadIdx.x < 32) {
        int w = wsum[threadIdx.x];
#pragma unroll
        for (int o = 1; o < 32; o <<= 1) {
            int y = __shfl_up_sync(0xffffffffu, w, o);
            if ((int)threadIdx.x >= o) w += y;
        }
        wsum[threadIdx.x] = w;
    }
    __syncthreads();
    int base = (warp > 0) ? wsum[warp - 1] : 0;
    int incl = base + x;
    if (i < N) g_rowptr[i] = incl - c;
    if (threadIdx.x == 1023) g_bsum[blockIdx.x] = incl;
}

// ---------------- #3 scan level 2+3 merged ------------------------------------
__global__ void k_scan23(int N, int E, int NB) {
    __shared__ int sb[128];
    int tid = threadIdx.x;
    if (tid < 128) sb[tid] = (tid < NB) ? g_bsum[tid] : 0;
    __syncthreads();
#pragma unroll
    for (int o = 1; o < 128; o <<= 1) {
        int v = 0;
        if (tid < 128 && tid >= o) v = sb[tid - o];
        __syncthreads();
        if (tid < 128) sb[tid] += v;
        __syncthreads();
    }
    int i = blockIdx.x * blockDim.x + tid;
    if (i < N) {
        int blk = i >> 10;
        int off = blk ? sb[blk - 1] : 0;
        int r = g_rowptr[i] + off;
        g_rowptr[i] = r;
        g_cursor[i] = r;
        g_dinv[i] = rsqrtf((float)g_cnt[i] + 1.0f);
    }
    if (i == 0) g_rowptr[N] = E;
}

// ---------------- #4 CSR fill -------------------------------------------------
__global__ void k_fill(const void* __restrict__ ei, long long E) {
    bool is64 = detect_is64((const unsigned int*)ei);
    long long e = (long long)blockIdx.x * blockDim.x + threadIdx.x;
    if (e >= E) return;
    int s, d;
    if (is64) {
        const long long* p = (const long long*)ei;
        s = (int)p[e]; d = (int)p[E + e];
    } else {
        const int* p = (const int*)ei;
        s = p[e]; d = p[E + e];
    }
    int pos = atomicAdd(&g_cursor[d], 1);
    g_adj[pos] = s;
}

// ---------------- fp32 store of u = a * dinv (coalesced, no repack) -----------
__device__ __forceinline__ void store_u(int n, int lane, float a0, float a1) {
    float dv = g_dinv[n];
    g_t[n * HID + lane]      = a0 * dv;
    g_t[n * HID + lane + 32] = a1 * dv;
}

// ---------------- #5 layer 0 fused: u = (relu(x@Win+bin) @ Wg0) * dinv --------
__global__ void k_layer0(const float* __restrict__ x, const float* __restrict__ Win,
                         const float* __restrict__ bin, const float* __restrict__ Wg,
                         int N) {
    __shared__ float Ws[HID * HID];
    __shared__ float Wi[12 * HID];
    __shared__ float bs[HID];
    for (int i = threadIdx.x; i < HID * HID; i += blockDim.x) Ws[i] = Wg[i];
    for (int i = threadIdx.x; i < 12 * HID; i += blockDim.x) Wi[i] = Win[i];
    if (threadIdx.x < HID) bs[threadIdx.x] = bin[threadIdx.x];
    __syncthreads();
    int lane = threadIdx.x & 31, warp = threadIdx.x >> 5;
    int nA = (blockIdx.x * (blockDim.x >> 5) + warp) * 2;
    int nB = nA + 1;
    if (nA >= N) return;
    bool hasB = nB < N;
    float xvA = lane < 12 ? x[nA * 12 + lane] : 0.f;
    float xvB = (hasB && lane < 12) ? x[nB * 12 + lane] : 0.f;
    float vloA = bs[lane], vhiA = bs[lane + 32];
    float vloB = vloA,     vhiB = vhiA;
#pragma unroll
    for (int c = 0; c < 12; c++) {
        float wlo = Wi[c * HID + lane], whi = Wi[c * HID + lane + 32];
        float xA = __shfl_sync(0xffffffffu, xvA, c);
        float xB = __shfl_sync(0xffffffffu, xvB, c);
        vloA = fmaf(xA, wlo, vloA); vhiA = fmaf(xA, whi, vhiA);
        vloB = fmaf(xB, wlo, vloB); vhiB = fmaf(xB, whi, vhiB);
    }
    vloA = fmaxf(vloA, 0.f); vhiA = fmaxf(vhiA, 0.f);
    vloB = fmaxf(vloB, 0.f); vhiB = fmaxf(vhiB, 0.f);
    float a0A = 0.f, a1A = 0.f, a0B = 0.f, a1B = 0.f;
#pragma unroll
    for (int c = 0; c < 32; c++) {
        float wlo = Ws[c * HID + lane], whi = Ws[c * HID + lane + 32];
        float xA = __shfl_sync(0xffffffffu, vloA, c);
        float xB = __shfl_sync(0xffffffffu, vloB, c);
        a0A = fmaf(xA, wlo, a0A); a1A = fmaf(xA, whi, a1A);
        a0B = fmaf(xB, wlo, a0B); a1B = fmaf(xB, whi, a1B);
    }
#pragma unroll
    for (int c = 0; c < 32; c++) {
        float wlo = Ws[(c + 32) * HID + lane], whi = Ws[(c + 32) * HID + lane + 32];
        float xA = __shfl_sync(0xffffffffu, vhiA, c);
        float xB = __shfl_sync(0xffffffffu, vhiB, c);
        a0A = fmaf(xA, wlo, a0A); a1A = fmaf(xA, whi, a1A);
        a0B = fmaf(xB, wlo, a0B); a1B = fmaf(xB, whi, a1B);
    }
    store_u(nA, lane, a0A, a1A);
    if (hasB) store_u(nB, lane, a0B, a1B);
}

// ---------------- layers 1,2: u = (relu(BN(agg)) @ Wg) * dinv -----------------
__global__ void k_gemm64(const float* __restrict__ Wg, const float* __restrict__ gamma,
                         const float* __restrict__ beta, int slot, int N) {
    __shared__ float Ws[HID * HID];
    for (int i = threadIdx.x; i < HID * HID; i += blockDim.x) Ws[i] = Wg[i];
    __syncthreads();
    int lane = threadIdx.x & 31, warp = threadIdx.x >> 5;
    float inv = 1.0f / (float)N;
    int c0 = lane, c1 = lane + 32;
    float mu0 = g_sum3[slot * HID + c0] * inv;
    float mu1 = g_sum3[slot * HID + c1] * inv;
    float v0 = g_sumsq3[slot * HID + c0] * inv - mu0 * mu0;
    float v1 = g_sumsq3[slot * HID + c1] * inv - mu1 * mu1;
    float sc0 = gamma[c0] * rsqrtf(v0 + EPSV);
    float sc1 = gamma[c1] * rsqrtf(v1 + EPSV);
    float sh0 = fmaf(-mu0, sc0, beta[c0]);
    float sh1 = fmaf(-mu1, sc1, beta[c1]);

    int nA = (blockIdx.x * (blockDim.x >> 5) + warp) * 2;
    int nB = nA + 1;
    if (nA >= N) return;
    bool hasB = nB < N;
    float vloA = fmaxf(fmaf(g_agg[nA * HID + c0], sc0, sh0), 0.f);
    float vhiA = fmaxf(fmaf(g_agg[nA * HID + c1], sc1, sh1), 0.f);
    float vloB = 0.f, vhiB = 0.f;
    if (hasB) {
        vloB = fmaxf(fmaf(g_agg[nB * HID + c0], sc0, sh0), 0.f);
        vhiB = fmaxf(fmaf(g_agg[nB * HID + c1], sc1, sh1), 0.f);
    }
    float a0A = 0.f, a1A = 0.f, a0B = 0.f, a1B = 0.f;
#pragma unroll
    for (int c = 0; c < 32; c++) {
        float wlo = Ws[c * HID + lane], whi = Ws[c * HID + lane + 32];
        float xA = __shfl_sync(0xffffffffu, vloA, c);
        float xB = __shfl_sync(0xffffffffu, vloB, c);
        a0A = fmaf(xA, wlo, a0A); a1A = fmaf(xA, whi, a1A);
        a0B = fmaf(xB, wlo, a0B); a1B = fmaf(xB, whi, a1B);
    }
#pragma unroll
    for (int c = 0; c < 32; c++) {
        float wlo = Ws[(c + 32) * HID + lane], whi = Ws[(c + 32) * HID + lane + 32];
        float xA = __shfl_sync(0xffffffffu, vhiA, c);
        float xB = __shfl_sync(0xffffffffu, vhiB, c);
        a0A = fmaf(xA, wlo, a0A); a1A = fmaf(xA, whi, a1A);
        a0B = fmaf(xB, wlo, a0B); a1B = fmaf(xB, whi, a1B);
    }
    store_u(nA, lane, a0A, a1A);
    if (hasB) store_u(nB, lane, a0B, a1B);
}

// ---------------- CSR gather + fused BN stats (fp32 rows: LDG.128, no cvts) ---
__global__ void k_agg(const float* __restrict__ bg, int slot, int N) {
    __shared__ float ss[HID], sq[HID];
    if (threadIdx.x < HID) { ss[threadIdx.x] = 0.f; sq[threadIdx.x] = 0.f; }
    __syncthreads();

    int lane = threadIdx.x & 31;
    int half = lane >> 4;
    int hl   = lane & 15;
    int warp_g = (int)((blockIdx.x * blockDim.x + threadIdx.x) >> 5);
    int nwarps = (int)((gridDim.x * blockDim.x) >> 5);

    const float4* __restrict__ u4 = (const float4*)g_t;
    float4 bvec = ((const float4*)bg)[hl];

    float4 s1 = {0.f, 0.f, 0.f, 0.f};
    float4 s2 = {0.f, 0.f, 0.f, 0.f};

    for (int n = warp_g; n < N; n += nwarps) {
        int beg = g_rowptr[n], end = g_rowptr[n + 1];
        float dv = g_dinv[n];
        float4 acc = {0.f, 0.f, 0.f, 0.f};
        if (half == 0) acc = u4[(long long)n * 16 + hl];   // self term u[d]

        int i = beg + half;
        for (; i + 14 < end; i += 16) {
            int e0 = g_adj[i],      e1 = g_adj[i + 2];
            int e2 = g_adj[i + 4],  e3 = g_adj[i + 6];
            int e4 = g_adj[i + 8],  e5 = g_adj[i + 10];
            int e6 = g_adj[i + 12], e7 = g_adj[i + 14];
            float4 v0 = u4[(long long)e0 * 16 + hl];
            float4 v1 = u4[(long long)e1 * 16 + hl];
            float4 v2 = u4[(long long)e2 * 16 + hl];
            float4 v3 = u4[(long long)e3 * 16 + hl];
            float4 v4 = u4[(long long)e4 * 16 + hl];
            float4 v5 = u4[(long long)e5 * 16 + hl];
            float4 v6 = u4[(long long)e6 * 16 + hl];
            float4 v7 = u4[(long long)e7 * 16 + hl];
            acc.x += ((v0.x + v1.x) + (v2.x + v3.x)) + ((v4.x + v5.x) + (v6.x + v7.x));
            acc.y += ((v0.y + v1.y) + (v2.y + v3.y)) + ((v4.y + v5.y) + (v6.y + v7.y));
            acc.z += ((v0.z + v1.z) + (v2.z + v3.z)) + ((v4.z + v5.z) + (v6.z + v7.z));
            acc.w += ((v0.w + v1.w) + (v2.w + v3.w)) + ((v4.w + v5.w) + (v6.w + v7.w));
        }
        for (; i + 6 < end; i += 8) {
            int e0 = g_adj[i],     e1 = g_adj[i + 2];
            int e2 = g_adj[i + 4], e3 = g_adj[i + 6];
            float4 v0 = u4[(long long)e0 * 16 + hl];
            float4 v1 = u4[(long long)e1 * 16 + hl];
            float4 v2 = u4[(long long)e2 * 16 + hl];
            float4 v3 = u4[(long long)e3 * 16 + hl];
            acc.x += (v0.x + v1.x) + (v2.x + v3.x);
            acc.y += (v0.y + v1.y) + (v2.y + v3.y);
            acc.z += (v0.z + v1.z) + (v2.z + v3.z);
            acc.w += (v0.w + v1.w) + (v2.w + v3.w);
        }
        for (; i < end; i += 2) {
            int s = g_adj[i];
            float4 v = u4[(long long)s * 16 + hl];
            acc.x += v.x; acc.y += v.y; acc.z += v.z; acc.w += v.w;
        }
        acc.x += __shfl_xor_sync(0xffffffffu, acc.x, 16);
        acc.y += __shfl_xor_sync(0xffffffffu, acc.y, 16);
        acc.z += __shfl_xor_sync(0xffffffffu, acc.z, 16);
        acc.w += __shfl_xor_sync(0xffffffffu, acc.w, 16);

        if (half == 0) {
            float4 o;
            o.x = fmaf(acc.x, dv, bvec.x);
            o.y = fmaf(acc.y, dv, bvec.y);
            o.z = fmaf(acc.z, dv, bvec.z);
            o.w = fmaf(acc.w, dv, bvec.w);
            ((float4*)g_agg)[(long long)n * 16 + hl] = o;
            s1.x += o.x; s1.y += o.y; s1.z += o.z; s1.w += o.w;
            s2.x = fmaf(o.x, o.x, s2.x); s2.y = fmaf(o.y, o.y, s2.y);
            s2.z = fmaf(o.z, o.z, s2.z); s2.w = fmaf(o.w, o.w, s2.w);
        }
    }

    if (half == 0) {
        atomicAdd(&ss[4 * hl + 0], s1.x); atomicAdd(&ss[4 * hl + 1], s1.y);
        atomicAdd(&ss[4 * hl + 2], s1.z); atomicAdd(&ss[4 * hl + 3], s1.w);
        atomicAdd(&sq[4 * hl + 0], s2.x); atomicAdd(&sq[4 * hl + 1], s2.y);
        atomicAdd(&sq[4 * hl + 2], s2.z); atomicAdd(&sq[4 * hl + 3], s2.w);
    }
    __syncthreads();
    if (threadIdx.x < HID) {
        atomicAdd(&g_sum3[slot * HID + threadIdx.x],   ss[threadIdx.x]);
        atomicAdd(&g_sumsq3[slot * HID + threadIdx.x], sq[threadIdx.x]);
    }
}

// ---------------- classifier + cleanup (re-zero g_cnt for next replay) -------
__global__ void k_classifier(const float* __restrict__ Wc1, const float* __restrict__ bc1,
                             const float* __restrict__ Wc2, const float* __restrict__ bc2,
                             const float* __restrict__ gamma, const float* __restrict__ beta,
                             float* __restrict__ out, int N) {
    int gid = blockIdx.x * blockDim.x + threadIdx.x;
    if (gid < N) g_cnt[gid] = 0;   // cleanup for next graph replay

    __shared__ float W1[64 * 32];
    __shared__ float W2[64];
    __shared__ float b1s[32];
    __shared__ float b2s[2];
    for (int i = threadIdx.x; i < 64 * 32; i += blockDim.x) W1[i] = Wc1[i];
    if (threadIdx.x < 64) W2[threadIdx.x] = Wc2[threadIdx.x];
    if (threadIdx.x < 32) b1s[threadIdx.x] = bc1[threadIdx.x];
    if (threadIdx.x < 2)  b2s[threadIdx.x] = bc2[threadIdx.x];
    __syncthreads();
    int lane = threadIdx.x & 31, warp = threadIdx.x >> 5;
    int n = blockIdx.x * (blockDim.x >> 5) + warp;
    if (n >= N) return;
    float inv = 1.0f / (float)N;
    int c0 = lane, c1 = lane + 32;
    float mu0 = g_sum3[2 * HID + c0] * inv;
    float mu1 = g_sum3[2 * HID + c1] * inv;
    float v0 = g_sumsq3[2 * HID + c0] * inv - mu0 * mu0;
    float v1 = g_sumsq3[2 * HID + c1] * inv - mu1 * mu1;
    float sc0 = gamma[c0] * rsqrtf(v0 + EPSV);
    float sc1 = gamma[c1] * rsqrtf(v1 + EPSV);
    float sh0 = fmaf(-mu0, sc0, beta[c0]);
    float sh1 = fmaf(-mu1, sc1, beta[c1]);

    float vlo = fmaf(g_agg[n * HID + c0], sc0, sh0);
    float vhi = fmaf(g_agg[n * HID + c1], sc1, sh1);
    float u = b1s[lane];
#pragma unroll
    for (int c = 0; c < 32; c++) {
        float xc = __shfl_sync(0xffffffffu, vlo, c);
        u = fmaf(xc, W1[c * 32 + lane], u);
    }
#pragma unroll
    for (int c = 0; c < 32; c++) {
        float xc = __shfl_sync(0xffffffffu, vhi, c);
        u = fmaf(xc, W1[(c + 32) * 32 + lane], u);
    }
    u = fmaxf(u, 0.f);
    float p0 = u * W2[lane * 2], p1 = u * W2[lane * 2 + 1];
#pragma unroll
    for (int o = 16; o > 0; o >>= 1) {
        p0 += __shfl_xor_sync(0xffffffffu, p0, o);
        p1 += __shfl_xor_sync(0xffffffffu, p1, o);
    }
    if (lane == 0) {
        out[n * 2]     = p0 + b2s[0];
        out[n * 2 + 1] = p1 + b2s[1];
    }
}

// ---------------- launch ------------------------------------------------------
extern "C" void kernel_launch(void* const* d_in, const int* in_sizes, int n_in,
                              void* d_out, int out_size) {
    const float* x    = (const float*)d_in[0];
    const void*  ei   = d_in[1];
    const float* W_in = (const float*)d_in[2];
    const float* b_in = (const float*)d_in[3];
    const float* W_g  = (const float*)d_in[4];
    const float* b_g  = (const float*)d_in[5];
    const float* gam  = (const float*)d_in[6];
    const float* bet  = (const float*)d_in[7];
    const float* W_c1 = (const float*)d_in[8];
    const float* b_c1 = (const float*)d_in[9];
    const float* W_c2 = (const float*)d_in[10];
    const float* b_c2 = (const float*)d_in[11];
    float* out = (float*)d_out;

    int N = in_sizes[0] / 12;
    long long E = (long long)in_sizes[1] / 2;

    const int TB = 256;
    unsigned nBlocks = (unsigned)((N + TB - 1) / TB);
    unsigned eBlocks = (unsigned)((E + TB - 1) / TB);
    int NB = (N + 1023) / 1024;
    unsigned gBlocks = (unsigned)((N + 15) / 16);   // 2 nodes/warp, 8 warps/block

    k_cnt<<<eBlocks, TB>>>(ei, E);                          // #1
    k_scan1<<<(unsigned)NB, 1024>>>(N);                     // #2
    k_scan23<<<nBlocks, TB>>>(N, (int)E, NB);               // #3
    k_fill<<<eBlocks, TB>>>(ei, E);                         // #4 <- profiled

    k_layer0<<<gBlocks, 256>>>(x, W_in, b_in, W_g, N);      // #5
    k_agg<<<2048, 256>>>(b_g, 0, N);                        // #6
    for (int l = 1; l < 3; l++) {
        k_gemm64<<<gBlocks, 256>>>(W_g + (long long)l * HID * HID,
                                   gam + (l - 1) * HID, bet + (l - 1) * HID,
                                   l - 1, N);
        k_agg<<<2048, 256>>>(b_g + l * HID, l, N);
    }
    k_classifier<<<(unsigned)((N + 7) / 8), 256>>>(W_c1, b_c1, W_c2, b_c2,
                                                   gam + 2 * HID, bet + 2 * HID,
                                                   out, N);
}

// round 9
// speedup vs baseline: 2.0309x; 1.1170x over previous
#include <cuda_runtime.h>
#include <cuda_fp16.h>
#include <cstdint>

#define MAXN 100000
#define MAXE 3200000
#define HID 64
#define EPSV 1e-5f

// ---------------- device scratch (zero-initialized at module load) -----------
__device__ __align__(128) float        g_dinv[MAXN];
__device__ __align__(128) unsigned int g_t16[MAXN * 32];    // u as half2 (64 half / row)
__device__ __align__(128) float        g_agg[MAXN * HID];   // aggregated pre-BN features
__device__ __align__(128) int          g_adj[MAXE];         // CSR column (src) indices
__device__ __align__(128) int          g_cnt[MAXN];         // zeroed by classifier epilogue
__device__ __align__(128) int          g_rowptr[MAXN + 1];
__device__ __align__(128) int          g_cursor[MAXN];
__device__ __align__(128) int          g_bsum[1024];
__device__ float g_sum3[3 * HID];     // per-layer BN sums (zeroed in k_cnt)
__device__ float g_sumsq3[3 * HID];

// ---------------- dtype detect: warp-uniform ballot on first 32 odd words -----
__device__ __forceinline__ bool detect_is64(const unsigned int* raw) {
    unsigned v = raw[2 * (threadIdx.x & 31) + 1];
    return __ballot_sync(0xffffffffu, v != 0u) == 0u;
}

// ---------------- #1 count in-degree (+ zero BN stat slots) -------------------
__global__ void k_cnt(const void* __restrict__ ei, long long E) {
    bool is64 = detect_is64((const unsigned int*)ei);
    if (blockIdx.x == 0 && threadIdx.x < 3 * HID) {
        g_sum3[threadIdx.x] = 0.f; g_sumsq3[threadIdx.x] = 0.f;
    }
    long long e = (long long)blockIdx.x * blockDim.x + threadIdx.x;
    if (e >= E) return;
    int d = is64 ? (int)((const long long*)ei)[E + e] : ((const int*)ei)[E + e];
    atomicAdd(&g_cnt[d], 1);
}

// ---------------- #2 scan level 1: per-1024-block exclusive scan --------------
__global__ void k_scan1(int N) {
    __shared__ int wsum[32];
    int i = blockIdx.x * 1024 + threadIdx.x;
    int lane = threadIdx.x & 31, warp = threadIdx.x >> 5;
    int c = (i < N) ? g_cnt[i] : 0;
    int x = c;
#pragma unroll
    for (int o = 1; o < 32; o <<= 1) {
        int y = __shfl_up_sync(0xffffffffu, x, o);
        if (lane >= o) x += y;
    }
    if (lane == 31) wsum[warp] = x;
    __syncthreads();
    if (threadIdx.x < 32) {
        int w = wsum[threadIdx.x];
#pragma unroll
        for (int o = 1; o < 32; o <<= 1) {
            int y = __shfl_up_sync(0xffffffffu, w, o);
            if ((int)threadIdx.x >= o) w += y;
        }
        wsum[threadIdx.x] = w;
    }
    __syncthreads();
    int base = (warp > 0) ? wsum[warp - 1] : 0;
    int incl = base + x;
    if (i < N) g_rowptr[i] = incl - c;
    if (threadIdx.x == 1023) g_bsum[blockIdx.x] = incl;
}

// ---------------- #3 scan level 2+3 merged ------------------------------------
__global__ void k_scan23(int N, int E, int NB) {
    __shared__ int sb[128];
    int tid = threadIdx.x;
    if (tid < 128) sb[tid] = (tid < NB) ? g_bsum[tid] : 0;
    __syncthreads();
#pragma unroll
    for (int o = 1; o < 128; o <<= 1) {
        int v = 0;
        if (tid < 128 && tid >= o) v = sb[tid - o];
        __syncthreads();
        if (tid < 128) sb[tid] += v;
        __syncthreads();
    }
    int i = blockIdx.x * blockDim.x + tid;
    if (i < N) {
        int blk = i >> 10;
        int off = blk ? sb[blk - 1] : 0;
        int r = g_rowptr[i] + off;
        g_rowptr[i] = r;
        g_cursor[i] = r;
        g_dinv[i] = rsqrtf((float)g_cnt[i] + 1.0f);
    }
    if (i == 0) g_rowptr[N] = E;
}

// ---------------- #4 CSR fill -------------------------------------------------
__global__ void k_fill(const void* __restrict__ ei, long long E) {
    bool is64 = detect_is64((const unsigned int*)ei);
    long long e = (long long)blockIdx.x * blockDim.x + threadIdx.x;
    if (e >= E) return;
    int s, d;
    if (is64) {
        const long long* p = (const long long*)ei;
        s = (int)p[e]; d = (int)p[E + e];
    } else {
        const int* p = (const int*)ei;
        s = p[e]; d = p[E + e];
    }
    int pos = atomicAdd(&g_cursor[d], 1);
    g_adj[pos] = s;
}

// ---------------- fp16 repack+store of u = a * dinv ---------------------------
__device__ __forceinline__ void store_u16(int n, int lane, float a0, float a1) {
    float dv = g_dinv[n];
    a0 *= dv; a1 *= dv;
    int idx0 = (2 * lane) & 31;
    float lo_a0 = __shfl_sync(0xffffffffu, a0, idx0);
    float hi_a0 = __shfl_sync(0xffffffffu, a0, idx0 + 1);
    float lo_a1 = __shfl_sync(0xffffffffu, a1, idx0);
    float hi_a1 = __shfl_sync(0xffffffffu, a1, idx0 + 1);
    float lo = lane < 16 ? lo_a0 : lo_a1;
    float hi = lane < 16 ? hi_a0 : hi_a1;
    __half2 hp = __floats2half2_rn(lo, hi);
    g_t16[n * 32 + lane] = *(unsigned int*)&hp;
}

// ---------------- #5 layer 0 fused: u = (relu(x@Win+bin) @ Wg0) * dinv --------
__global__ void k_layer0(const float* __restrict__ x, const float* __restrict__ Win,
                         const float* __restrict__ bin, const float* __restrict__ Wg,
                         int N) {
    __shared__ float Ws[HID * HID];
    __shared__ float Wi[12 * HID];
    __shared__ float bs[HID];
    for (int i = threadIdx.x; i < HID * HID; i += blockDim.x) Ws[i] = Wg[i];
    for (int i = threadIdx.x; i < 12 * HID; i += blockDim.x) Wi[i] = Win[i];
    if (threadIdx.x < HID) bs[threadIdx.x] = bin[threadIdx.x];
    __syncthreads();
    int lane = threadIdx.x & 31, warp = threadIdx.x >> 5;
    int nA = (blockIdx.x * (blockDim.x >> 5) + warp) * 2;
    int nB = nA + 1;
    if (nA >= N) return;
    bool hasB = nB < N;
    float xvA = lane < 12 ? x[nA * 12 + lane] : 0.f;
    float xvB = (hasB && lane < 12) ? x[nB * 12 + lane] : 0.f;
    float vloA = bs[lane], vhiA = bs[lane + 32];
    float vloB = vloA,     vhiB = vhiA;
#pragma unroll
    for (int c = 0; c < 12; c++) {
        float wlo = Wi[c * HID + lane], whi = Wi[c * HID + lane + 32];
        float xA = __shfl_sync(0xffffffffu, xvA, c);
        float xB = __shfl_sync(0xffffffffu, xvB, c);
        vloA = fmaf(xA, wlo, vloA); vhiA = fmaf(xA, whi, vhiA);
        vloB = fmaf(xB, wlo, vloB); vhiB = fmaf(xB, whi, vhiB);
    }
    vloA = fmaxf(vloA, 0.f); vhiA = fmaxf(vhiA, 0.f);
    vloB = fmaxf(vloB, 0.f); vhiB = fmaxf(vhiB, 0.f);
    float a0A = 0.f, a1A = 0.f, a0B = 0.f, a1B = 0.f;
#pragma unroll
    for (int c = 0; c < 32; c++) {
        float wlo = Ws[c * HID + lane], whi = Ws[c * HID + lane + 32];
        float xA = __shfl_sync(0xffffffffu, vloA, c);
        float xB = __shfl_sync(0xffffffffu, vloB, c);
        a0A = fmaf(xA, wlo, a0A); a1A = fmaf(xA, whi, a1A);
        a0B = fmaf(xB, wlo, a0B); a1B = fmaf(xB, whi, a1B);
    }
#pragma unroll
    for (int c = 0; c < 32; c++) {
        float wlo = Ws[(c + 32) * HID + lane], whi = Ws[(c + 32) * HID + lane + 32];
        float xA = __shfl_sync(0xffffffffu, vhiA, c);
        float xB = __shfl_sync(0xffffffffu, vhiB, c);
        a0A = fmaf(xA, wlo, a0A); a1A = fmaf(xA, whi, a1A);
        a0B = fmaf(xB, wlo, a0B); a1B = fmaf(xB, whi, a1B);
    }
    store_u16(nA, lane, a0A, a1A);
    if (hasB) store_u16(nB, lane, a0B, a1B);
}

// ---------------- layers 1,2: u = (relu(BN(agg)) @ Wg) * dinv -----------------
__global__ void k_gemm64(const float* __restrict__ Wg, const float* __restrict__ gamma,
                         const float* __restrict__ beta, int slot, int N) {
    __shared__ float Ws[HID * HID];
    for (int i = threadIdx.x; i < HID * HID; i += blockDim.x) Ws[i] = Wg[i];
    __syncthreads();
    int lane = threadIdx.x & 31, warp = threadIdx.x >> 5;
    float inv = 1.0f / (float)N;
    int c0 = lane, c1 = lane + 32;
    float mu0 = g_sum3[slot * HID + c0] * inv;
    float mu1 = g_sum3[slot * HID + c1] * inv;
    float v0 = g_sumsq3[slot * HID + c0] * inv - mu0 * mu0;
    float v1 = g_sumsq3[slot * HID + c1] * inv - mu1 * mu1;
    float sc0 = gamma[c0] * rsqrtf(v0 + EPSV);
    float sc1 = gamma[c1] * rsqrtf(v1 + EPSV);
    float sh0 = fmaf(-mu0, sc0, beta[c0]);
    float sh1 = fmaf(-mu1, sc1, beta[c1]);

    int nA = (blockIdx.x * (blockDim.x >> 5) + warp) * 2;
    int nB = nA + 1;
    if (nA >= N) return;
    bool hasB = nB < N;
    float vloA = fmaxf(fmaf(g_agg[nA * HID + c0], sc0, sh0), 0.f);
    float vhiA = fmaxf(fmaf(g_agg[nA * HID + c1], sc1, sh1), 0.f);
    float vloB = 0.f, vhiB = 0.f;
    if (hasB) {
        vloB = fmaxf(fmaf(g_agg[nB * HID + c0], sc0, sh0), 0.f);
        vhiB = fmaxf(fmaf(g_agg[nB * HID + c1], sc1, sh1), 0.f);
    }
    float a0A = 0.f, a1A = 0.f, a0B = 0.f, a1B = 0.f;
#pragma unroll
    for (int c = 0; c < 32; c++) {
        float wlo = Ws[c * HID + lane], whi = Ws[c * HID + lane + 32];
        float xA = __shfl_sync(0xffffffffu, vloA, c);
        float xB = __shfl_sync(0xffffffffu, vloB, c);
        a0A = fmaf(xA, wlo, a0A); a1A = fmaf(xA, whi, a1A);
        a0B = fmaf(xB, wlo, a0B); a1B = fmaf(xB, whi, a1B);
    }
#pragma unroll
    for (int c = 0; c < 32; c++) {
        float wlo = Ws[(c + 32) * HID + lane], whi = Ws[(c + 32) * HID + lane + 32];
        float xA = __shfl_sync(0xffffffffu, vhiA, c);
        float xB = __shfl_sync(0xffffffffu, vhiB, c);
        a0A = fmaf(xA, wlo, a0A); a1A = fmaf(xA, whi, a1A);
        a0B = fmaf(xB, wlo, a0B); a1B = fmaf(xB, whi, a1B);
    }
    store_u16(nA, lane, a0A, a1A);
    if (hasB) store_u16(nB, lane, a0B, a1B);
}

// ---------------- CSR gather + fused BN stats ---------------------------------
// Warp per node; half-warp owns a uint2 (4 half) chunk; halves alternate edges.
// Pairwise HADD2 on adjacent edges halves the convert/accumulate instructions.
__global__ void k_agg(const float* __restrict__ bg, int slot, int N) {
    __shared__ float ss[HID], sq[HID];
    if (threadIdx.x < HID) { ss[threadIdx.x] = 0.f; sq[threadIdx.x] = 0.f; }
    __syncthreads();

    int lane = threadIdx.x & 31;
    int half = lane >> 4;
    int hl   = lane & 15;
    int warp_g = (int)((blockIdx.x * blockDim.x + threadIdx.x) >> 5);
    int nwarps = (int)((gridDim.x * blockDim.x) >> 5);

    const uint2* __restrict__ u2 = (const uint2*)g_t16;
    float4 bvec = ((const float4*)bg)[hl];

    float4 s1 = {0.f, 0.f, 0.f, 0.f};
    float4 s2 = {0.f, 0.f, 0.f, 0.f};

    for (int n = warp_g; n < N; n += nwarps) {
        int beg = g_rowptr[n], end = g_rowptr[n + 1];
        float dv = g_dinv[n];
        float4 acc = {0.f, 0.f, 0.f, 0.f};
        if (half == 0) {
            uint2 sv = u2[n * 16 + hl];
            float2 f0 = __half22float2(*(__half2*)&sv.x);
            float2 f1 = __half22float2(*(__half2*)&sv.y);
            acc.x = f0.x; acc.y = f0.y; acc.z = f1.x; acc.w = f1.y;
        }

        int i = beg + half;
        for (; i + 14 < end; i += 16) {
            int e0 = g_adj[i],      e1 = g_adj[i + 2];
            int e2 = g_adj[i + 4],  e3 = g_adj[i + 6];
            int e4 = g_adj[i + 8],  e5 = g_adj[i + 10];
            int e6 = g_adj[i + 12], e7 = g_adj[i + 14];
            uint2 v0 = u2[e0 * 16 + hl], v1 = u2[e1 * 16 + hl];
            uint2 v2 = u2[e2 * 16 + hl], v3 = u2[e3 * 16 + hl];
            uint2 v4 = u2[e4 * 16 + hl], v5 = u2[e5 * 16 + hl];
            uint2 v6 = u2[e6 * 16 + hl], v7 = u2[e7 * 16 + hl];
            // pairwise fp16 adds (one extra fp16 rounding per pair)
            __half2 p0x = __hadd2(*(__half2*)&v0.x, *(__half2*)&v1.x);
            __half2 p0y = __hadd2(*(__half2*)&v0.y, *(__half2*)&v1.y);
            __half2 p1x = __hadd2(*(__half2*)&v2.x, *(__half2*)&v3.x);
            __half2 p1y = __hadd2(*(__half2*)&v2.y, *(__half2*)&v3.y);
            __half2 p2x = __hadd2(*(__half2*)&v4.x, *(__half2*)&v5.x);
            __half2 p2y = __hadd2(*(__half2*)&v4.y, *(__half2*)&v5.y);
            __half2 p3x = __hadd2(*(__half2*)&v6.x, *(__half2*)&v7.x);
            __half2 p3y = __hadd2(*(__half2*)&v6.y, *(__half2*)&v7.y);
            float2 f0x = __half22float2(p0x), f0y = __half22float2(p0y);
            float2 f1x = __half22float2(p1x), f1y = __half22float2(p1y);
            float2 f2x = __half22float2(p2x), f2y = __half22float2(p2y);
            float2 f3x = __half22float2(p3x), f3y = __half22float2(p3y);
            acc.x += (f0x.x + f1x.x) + (f2x.x + f3x.x);
            acc.y += (f0x.y + f1x.y) + (f2x.y + f3x.y);
            acc.z += (f0y.x + f1y.x) + (f2y.x + f3y.x);
            acc.w += (f0y.y + f1y.y) + (f2y.y + f3y.y);
        }
        for (; i + 6 < end; i += 8) {
            int e0 = g_adj[i],     e1 = g_adj[i + 2];
            int e2 = g_adj[i + 4], e3 = g_adj[i + 6];
            uint2 v0 = u2[e0 * 16 + hl], v1 = u2[e1 * 16 + hl];
            uint2 v2 = u2[e2 * 16 + hl], v3 = u2[e3 * 16 + hl];
            __half2 p0x = __hadd2(*(__half2*)&v0.x, *(__half2*)&v1.x);
            __half2 p0y = __hadd2(*(__half2*)&v0.y, *(__half2*)&v1.y);
            __half2 p1x = __hadd2(*(__half2*)&v2.x, *(__half2*)&v3.x);
            __half2 p1y = __hadd2(*(__half2*)&v2.y, *(__half2*)&v3.y);
            float2 f0x = __half22float2(p0x), f0y = __half22float2(p0y);
            float2 f1x = __half22float2(p1x), f1y = __half22float2(p1y);
            acc.x += f0x.x + f1x.x;
            acc.y += f0x.y + f1x.y;
            acc.z += f0y.x + f1y.x;
            acc.w += f0y.y + f1y.y;
        }
        for (; i < end; i += 2) {
            int s = g_adj[i];
            uint2 v = u2[s * 16 + hl];
            float2 f0 = __half22float2(*(__half2*)&v.x);
            float2 f1 = __half22float2(*(__half2*)&v.y);
            acc.x += f0.x; acc.y += f0.y; acc.z += f1.x; acc.w += f1.y;
        }
        acc.x += __shfl_xor_sync(0xffffffffu, acc.x, 16);
        acc.y += __shfl_xor_sync(0xffffffffu, acc.y, 16);
        acc.z += __shfl_xor_sync(0xffffffffu, acc.z, 16);
        acc.w += __shfl_xor_sync(0xffffffffu, acc.w, 16);

        if (half == 0) {
            float4 o;
            o.x = fmaf(acc.x, dv, bvec.x);
            o.y = fmaf(acc.y, dv, bvec.y);
            o.z = fmaf(acc.z, dv, bvec.z);
            o.w = fmaf(acc.w, dv, bvec.w);
            ((float4*)g_agg)[(long long)n * 16 + hl] = o;
            s1.x += o.x; s1.y += o.y; s1.z += o.z; s1.w += o.w;
            s2.x = fmaf(o.x, o.x, s2.x); s2.y = fmaf(o.y, o.y, s2.y);
            s2.z = fmaf(o.z, o.z, s2.z); s2.w = fmaf(o.w, o.w, s2.w);
        }
    }

    if (half == 0) {
        atomicAdd(&ss[4 * hl + 0], s1.x); atomicAdd(&ss[4 * hl + 1], s1.y);
        atomicAdd(&ss[4 * hl + 2], s1.z); atomicAdd(&ss[4 * hl + 3], s1.w);
        atomicAdd(&sq[4 * hl + 0], s2.x); atomicAdd(&sq[4 * hl + 1], s2.y);
        atomicAdd(&sq[4 * hl + 2], s2.z); atomicAdd(&sq[4 * hl + 3], s2.w);
    }
    __syncthreads();
    if (threadIdx.x < HID) {
        atomicAdd(&g_sum3[slot * HID + threadIdx.x],   ss[threadIdx.x]);
        atomicAdd(&g_sumsq3[slot * HID + threadIdx.x], sq[threadIdx.x]);
    }
}

// ---------------- classifier + cleanup (re-zero g_cnt for next replay) -------
__global__ void k_classifier(const float* __restrict__ Wc1, const float* __restrict__ bc1,
                             const float* __restrict__ Wc2, const float* __restrict__ bc2,
                             const float* __restrict__ gamma, const float* __restrict__ beta,
                             float* __restrict__ out, int N) {
    int gid = blockIdx.x * blockDim.x + threadIdx.x;
    if (gid < N) g_cnt[gid] = 0;   // cleanup for next graph replay

    __shared__ float W1[64 * 32];
    __shared__ float W2[64];
    __shared__ float b1s[32];
    __shared__ float b2s[2];
    for (int i = threadIdx.x; i < 64 * 32; i += blockDim.x) W1[i] = Wc1[i];
    if (threadIdx.x < 64) W2[threadIdx.x] = Wc2[threadIdx.x];
    if (threadIdx.x < 32) b1s[threadIdx.x] = bc1[threadIdx.x];
    if (threadIdx.x < 2)  b2s[threadIdx.x] = bc2[threadIdx.x];
    __syncthreads();
    int lane = threadIdx.x & 31, warp = threadIdx.x >> 5;
    int n = blockIdx.x * (blockDim.x >> 5) + warp;
    if (n >= N) return;
    float inv = 1.0f / (float)N;
    int c0 = lane, c1 = lane + 32;
    float mu0 = g_sum3[2 * HID + c0] * inv;
    float mu1 = g_sum3[2 * HID + c1] * inv;
    float v0 = g_sumsq3[2 * HID + c0] * inv - mu0 * mu0;
    float v1 = g_sumsq3[2 * HID + c1] * inv - mu1 * mu1;
    float sc0 = gamma[c0] * rsqrtf(v0 + EPSV);
    float sc1 = gamma[c1] * rsqrtf(v1 + EPSV);
    float sh0 = fmaf(-mu0, sc0, beta[c0]);
    float sh1 = fmaf(-mu1, sc1, beta[c1]);

    float vlo = fmaf(g_agg[n * HID + c0], sc0, sh0);
    float vhi = fmaf(g_agg[n * HID + c1], sc1, sh1);
    float u = b1s[lane];
#pragma unroll
    for (int c = 0; c < 32; c++) {
        float xc = __shfl_sync(0xffffffffu, vlo, c);
        u = fmaf(xc, W1[c * 32 + lane], u);
    }
#pragma unroll
    for (int c = 0; c < 32; c++) {
        float xc = __shfl_sync(0xffffffffu, vhi, c);
        u = fmaf(xc, W1[(c + 32) * 32 + lane], u);
    }
    u = fmaxf(u, 0.f);
    float p0 = u * W2[lane * 2], p1 = u * W2[lane * 2 + 1];
#pragma unroll
    for (int o = 16; o > 0; o >>= 1) {
        p0 += __shfl_xor_sync(0xffffffffu, p0, o);
        p1 += __shfl_xor_sync(0xffffffffu, p1, o);
    }
    if (lane == 0) {
        out[n * 2]     = p0 + b2s[0];
        out[n * 2 + 1] = p1 + b2s[1];
    }
}

// ---------------- launch ------------------------------------------------------
extern "C" void kernel_launch(void* const* d_in, const int* in_sizes, int n_in,
                              void* d_out, int out_size) {
    const float* x    = (const float*)d_in[0];
    const void*  ei   = d_in[1];
    const float* W_in = (const float*)d_in[2];
    const float* b_in = (const float*)d_in[3];
    const float* W_g  = (const float*)d_in[4];
    const float* b_g  = (const float*)d_in[5];
    const float* gam  = (const float*)d_in[6];
    const float* bet  = (const float*)d_in[7];
    const float* W_c1 = (const float*)d_in[8];
    const float* b_c1 = (const float*)d_in[9];
    const float* W_c2 = (const float*)d_in[10];
    const float* b_c2 = (const float*)d_in[11];
    float* out = (float*)d_out;

    int N = in_sizes[0] / 12;
    long long E = (long long)in_sizes[1] / 2;

    const int TB = 256;
    unsigned nBlocks = (unsigned)((N + TB - 1) / TB);
    unsigned eBlocks = (unsigned)((E + TB - 1) / TB);
    int NB = (N + 1023) / 1024;
    unsigned gBlocks = (unsigned)((N + 15) / 16);   // 2 nodes/warp, 8 warps/block
    const unsigned AGG_BLOCKS = 1184;               // 148 SMs x 8 blocks: one full wave

    k_cnt<<<eBlocks, TB>>>(ei, E);                          // #1
    k_scan1<<<(unsigned)NB, 1024>>>(N);                     // #2
    k_scan23<<<nBlocks, TB>>>(N, (int)E, NB);               // #3
    k_fill<<<eBlocks, TB>>>(ei, E);                         // #4 <- profiled

    k_layer0<<<gBlocks, 256>>>(x, W_in, b_in, W_g, N);      // #5
    k_agg<<<AGG_BLOCKS, 256>>>(b_g, 0, N);                  // #6
    for (int l = 1; l < 3; l++) {
        k_gemm64<<<gBlocks, 256>>>(W_g + (long long)l * HID * HID,
                                   gam + (l - 1) * HID, bet + (l - 1) * HID,
                                   l - 1, N);
        k_agg<<<AGG_BLOCKS, 256>>>(b_g + l * HID, l, N);
    }
    k_classifier<<<(unsigned)((N + 7) / 8), 256>>>(W_c1, b_c1, W_c2, b_c2,
                                                   gam + 2 * HID, bet + 2 * HID,
                                                   out, N);
}

// round 10
// speedup vs baseline: 2.1197x; 1.0437x over previous
#include <cuda_runtime.h>
#include <cuda_fp16.h>
#include <cstdint>

#define MAXN 100000
#define MAXE 3200000
#define HID 64
#define EPSV 1e-5f

// ---------------- device scratch (zero-initialized at module load) -----------
__device__ __align__(128) float        g_dinv[MAXN];
__device__ __align__(128) unsigned int g_t16[MAXN * 32];    // u as half2 (64 half / row)
__device__ __align__(128) float        g_agg[MAXN * HID];   // aggregated pre-BN features
__device__ __align__(128) int          g_adj[MAXE];         // CSR column (src) indices
__device__ __align__(128) int          g_cnt[MAXN];         // zeroed by classifier epilogue
__device__ __align__(128) int          g_rowptr[MAXN + 1];
__device__ __align__(128) int          g_cursor[MAXN];
__device__ __align__(128) int          g_bsum[1024];
__device__ float g_sum3[3 * HID];     // per-layer BN sums (zeroed in k_cnt)
__device__ float g_sumsq3[3 * HID];

// ---------------- dtype detect: warp-uniform ballot on first 32 odd words -----
__device__ __forceinline__ bool detect_is64(const unsigned int* raw) {
    unsigned v = raw[2 * (threadIdx.x & 31) + 1];
    return __ballot_sync(0xffffffffu, v != 0u) == 0u;
}

// ---------------- #1 count in-degree (+ zero BN stat slots) -------------------
__global__ void k_cnt(const void* __restrict__ ei, long long E) {
    bool is64 = detect_is64((const unsigned int*)ei);
    if (blockIdx.x == 0 && threadIdx.x < 3 * HID) {
        g_sum3[threadIdx.x] = 0.f; g_sumsq3[threadIdx.x] = 0.f;
    }
    long long e = (long long)blockIdx.x * blockDim.x + threadIdx.x;
    if (e >= E) return;
    int d = is64 ? (int)((const long long*)ei)[E + e] : ((const int*)ei)[E + e];
    atomicAdd(&g_cnt[d], 1);
}

// ---------------- #2 scan level 1: per-1024-block exclusive scan --------------
__global__ void k_scan1(int N) {
    __shared__ int wsum[32];
    int i = blockIdx.x * 1024 + threadIdx.x;
    int lane = threadIdx.x & 31, warp = threadIdx.x >> 5;
    int c = (i < N) ? g_cnt[i] : 0;
    int x = c;
#pragma unroll
    for (int o = 1; o < 32; o <<= 1) {
        int y = __shfl_up_sync(0xffffffffu, x, o);
        if (lane >= o) x += y;
    }
    if (lane == 31) wsum[warp] = x;
    __syncthreads();
    if (threadIdx.x < 32) {
        int w = wsum[threadIdx.x];
#pragma unroll
        for (int o = 1; o < 32; o <<= 1) {
            int y = __shfl_up_sync(0xffffffffu, w, o);
            if ((int)threadIdx.x >= o) w += y;
        }
        wsum[threadIdx.x] = w;
    }
    __syncthreads();
    int base = (warp > 0) ? wsum[warp - 1] : 0;
    int incl = base + x;
    if (i < N) g_rowptr[i] = incl - c;
    if (threadIdx.x == 1023) g_bsum[blockIdx.x] = incl;
}

// ---------------- #3 scan level 2+3 merged ------------------------------------
__global__ void k_scan23(int N, int E, int NB) {
    __shared__ int sb[128];
    int tid = threadIdx.x;
    if (tid < 128) sb[tid] = (tid < NB) ? g_bsum[tid] : 0;
    __syncthreads();
#pragma unroll
    for (int o = 1; o < 128; o <<= 1) {
        int v = 0;
        if (tid < 128 && tid >= o) v = sb[tid - o];
        __syncthreads();
        if (tid < 128) sb[tid] += v;
        __syncthreads();
    }
    int i = blockIdx.x * blockDim.x + tid;
    if (i < N) {
        int blk = i >> 10;
        int off = blk ? sb[blk - 1] : 0;
        int r = g_rowptr[i] + off;
        g_rowptr[i] = r;
        g_cursor[i] = r;
        g_dinv[i] = rsqrtf((float)g_cnt[i] + 1.0f);
    }
    if (i == 0) g_rowptr[N] = E;
}

// ---------------- fp16 repack+store of u = a * dinv ---------------------------
__device__ __forceinline__ void store_u16(int n, int lane, float a0, float a1) {
    float dv = g_dinv[n];
    a0 *= dv; a1 *= dv;
    int idx0 = (2 * lane) & 31;
    float lo_a0 = __shfl_sync(0xffffffffu, a0, idx0);
    float hi_a0 = __shfl_sync(0xffffffffu, a0, idx0 + 1);
    float lo_a1 = __shfl_sync(0xffffffffu, a1, idx0);
    float hi_a1 = __shfl_sync(0xffffffffu, a1, idx0 + 1);
    float lo = lane < 16 ? lo_a0 : lo_a1;
    float hi = lane < 16 ? hi_a0 : hi_a1;
    __half2 hp = __floats2half2_rn(lo, hi);
    g_t16[n * 32 + lane] = *(unsigned int*)&hp;
}

// ---------------- #4 heterogeneous grid: CSR fill blocks + layer0 blocks ------
// Fill is atomic/latency bound (issue 7.8%), layer0 is FFMA bound; interleaving
// roles 2:1 co-schedules them on the same SMs. Both roles depend only on the
// scan (cursor/dinv), not on each other. Smem is warp-limit-neutral (8 blocks
// x 19.7KB = 158KB < 228KB).
__global__ void k_fill_layer0(const void* __restrict__ ei, long long E,
                              const float* __restrict__ x,
                              const float* __restrict__ Win,
                              const float* __restrict__ bin,
                              const float* __restrict__ Wg,
                              int N, int eB, int gB) {
    __shared__ float Ws[HID * HID];
    __shared__ float Wi[12 * HID];
    __shared__ float bs[HID];

    int bid = blockIdx.x;
    int k = bid / 3, m = bid - k * 3;

    if (m == 2) {
        // ---- layer0 role: u = (relu(x@Win+bin) @ Wg0) * dinv, 2 nodes/warp ----
        if (k >= gB) return;
        for (int i = threadIdx.x; i < HID * HID; i += blockDim.x) Ws[i] = Wg[i];
        for (int i = threadIdx.x; i < 12 * HID; i += blockDim.x) Wi[i] = Win[i];
        if (threadIdx.x < HID) bs[threadIdx.x] = bin[threadIdx.x];
        __syncthreads();
        int lane = threadIdx.x & 31, warp = threadIdx.x >> 5;
        int nA = (k * 8 + warp) * 2;
        int nB = nA + 1;
        if (nA >= N) return;
        bool hasB = nB < N;
        float xvA = lane < 12 ? x[nA * 12 + lane] : 0.f;
        float xvB = (hasB && lane < 12) ? x[nB * 12 + lane] : 0.f;
        float vloA = bs[lane], vhiA = bs[lane + 32];
        float vloB = vloA,     vhiB = vhiA;
#pragma unroll
        for (int c = 0; c < 12; c++) {
            float wlo = Wi[c * HID + lane], whi = Wi[c * HID + lane + 32];
            float xA = __shfl_sync(0xffffffffu, xvA, c);
            float xB = __shfl_sync(0xffffffffu, xvB, c);
            vloA = fmaf(xA, wlo, vloA); vhiA = fmaf(xA, whi, vhiA);
            vloB = fmaf(xB, wlo, vloB); vhiB = fmaf(xB, whi, vhiB);
        }
        vloA = fmaxf(vloA, 0.f); vhiA = fmaxf(vhiA, 0.f);
        vloB = fmaxf(vloB, 0.f); vhiB = fmaxf(vhiB, 0.f);
        float a0A = 0.f, a1A = 0.f, a0B = 0.f, a1B = 0.f;
#pragma unroll
        for (int c = 0; c < 32; c++) {
            float wlo = Ws[c * HID + lane], whi = Ws[c * HID + lane + 32];
            float xA = __shfl_sync(0xffffffffu, vloA, c);
            float xB = __shfl_sync(0xffffffffu, vloB, c);
            a0A = fmaf(xA, wlo, a0A); a1A = fmaf(xA, whi, a1A);
            a0B = fmaf(xB, wlo, a0B); a1B = fmaf(xB, whi, a1B);
        }
#pragma unroll
        for (int c = 0; c < 32; c++) {
            float wlo = Ws[(c + 32) * HID + lane], whi = Ws[(c + 32) * HID + lane + 32];
            float xA = __shfl_sync(0xffffffffu, vhiA, c);
            float xB = __shfl_sync(0xffffffffu, vhiB, c);
            a0A = fmaf(xA, wlo, a0A); a1A = fmaf(xA, whi, a1A);
            a0B = fmaf(xB, wlo, a0B); a1B = fmaf(xB, whi, a1B);
        }
        store_u16(nA, lane, a0A, a1A);
        if (hasB) store_u16(nB, lane, a0B, a1B);
        return;
    }

    // ---- fill role: scatter src into CSR slot -------------------------------
    int fid = 2 * k + m;
    if (fid >= eB) return;
    bool is64 = detect_is64((const unsigned int*)ei);
    long long e = (long long)fid * blockDim.x + threadIdx.x;
    if (e >= E) return;
    int s, d;
    if (is64) {
        const long long* p = (const long long*)ei;
        s = (int)p[e]; d = (int)p[E + e];
    } else {
        const int* p = (const int*)ei;
        s = p[e]; d = p[E + e];
    }
    int pos = atomicAdd(&g_cursor[d], 1);
    g_adj[pos] = s;
}

// ---------------- layers 1,2: u = (relu(BN(agg)) @ Wg) * dinv -----------------
__global__ void k_gemm64(const float* __restrict__ Wg, const float* __restrict__ gamma,
                         const float* __restrict__ beta, int slot, int N) {
    __shared__ float Ws[HID * HID];
    for (int i = threadIdx.x; i < HID * HID; i += blockDim.x) Ws[i] = Wg[i];
    __syncthreads();
    int lane = threadIdx.x & 31, warp = threadIdx.x >> 5;
    float inv = 1.0f / (float)N;
    int c0 = lane, c1 = lane + 32;
    float mu0 = g_sum3[slot * HID + c0] * inv;
    float mu1 = g_sum3[slot * HID + c1] * inv;
    float v0 = g_sumsq3[slot * HID + c0] * inv - mu0 * mu0;
    float v1 = g_sumsq3[slot * HID + c1] * inv - mu1 * mu1;
    float sc0 = gamma[c0] * rsqrtf(v0 + EPSV);
    float sc1 = gamma[c1] * rsqrtf(v1 + EPSV);
    float sh0 = fmaf(-mu0, sc0, beta[c0]);
    float sh1 = fmaf(-mu1, sc1, beta[c1]);

    int nA = (blockIdx.x * (blockDim.x >> 5) + warp) * 2;
    int nB = nA + 1;
    if (nA >= N) return;
    bool hasB = nB < N;
    float vloA = fmaxf(fmaf(g_agg[nA * HID + c0], sc0, sh0), 0.f);
    float vhiA = fmaxf(fmaf(g_agg[nA * HID + c1], sc1, sh1), 0.f);
    float vloB = 0.f, vhiB = 0.f;
    if (hasB) {
        vloB = fmaxf(fmaf(g_agg[nB * HID + c0], sc0, sh0), 0.f);
        vhiB = fmaxf(fmaf(g_agg[nB * HID + c1], sc1, sh1), 0.f);
    }
    float a0A = 0.f, a1A = 0.f, a0B = 0.f, a1B = 0.f;
#pragma unroll
    for (int c = 0; c < 32; c++) {
        float wlo = Ws[c * HID + lane], whi = Ws[c * HID + lane + 32];
        float xA = __shfl_sync(0xffffffffu, vloA, c);
        float xB = __shfl_sync(0xffffffffu, vloB, c);
        a0A = fmaf(xA, wlo, a0A); a1A = fmaf(xA, whi, a1A);
        a0B = fmaf(xB, wlo, a0B); a1B = fmaf(xB, whi, a1B);
    }
#pragma unroll
    for (int c = 0; c < 32; c++) {
        float wlo = Ws[(c + 32) * HID + lane], whi = Ws[(c + 32) * HID + lane + 32];
        float xA = __shfl_sync(0xffffffffu, vhiA, c);
        float xB = __shfl_sync(0xffffffffu, vhiB, c);
        a0A = fmaf(xA, wlo, a0A); a1A = fmaf(xA, whi, a1A);
        a0B = fmaf(xB, wlo, a0B); a1B = fmaf(xB, whi, a1B);
    }
    store_u16(nA, lane, a0A, a1A);
    if (hasB) store_u16(nB, lane, a0B, a1B);
}

// ---------------- CSR gather + fused BN stats ---------------------------------
// Warp per node; half-warp owns a uint2 (4 half) chunk; halves alternate edges.
// Pairwise HADD2 on adjacent edges halves the convert/accumulate instructions.
__global__ void k_agg(const float* __restrict__ bg, int slot, int N) {
    __shared__ float ss[HID], sq[HID];
    if (threadIdx.x < HID) { ss[threadIdx.x] = 0.f; sq[threadIdx.x] = 0.f; }
    __syncthreads();

    int lane = threadIdx.x & 31;
    int half = lane >> 4;
    int hl   = lane & 15;
    int warp_g = (int)((blockIdx.x * blockDim.x + threadIdx.x) >> 5);
    int nwarps = (int)((gridDim.x * blockDim.x) >> 5);

    const uint2* __restrict__ u2 = (const uint2*)g_t16;
    float4 bvec = ((const float4*)bg)[hl];

    float4 s1 = {0.f, 0.f, 0.f, 0.f};
    float4 s2 = {0.f, 0.f, 0.f, 0.f};

    for (int n = warp_g; n < N; n += nwarps) {
        int beg = g_rowptr[n], end = g_rowptr[n + 1];
        float dv = g_dinv[n];
        float4 acc = {0.f, 0.f, 0.f, 0.f};
        if (half == 0) {
            uint2 sv = u2[n * 16 + hl];
            float2 f0 = __half22float2(*(__half2*)&sv.x);
            float2 f1 = __half22float2(*(__half2*)&sv.y);
            acc.x = f0.x; acc.y = f0.y; acc.z = f1.x; acc.w = f1.y;
        }

        int i = beg + half;
        for (; i + 14 < end; i += 16) {
            int e0 = g_adj[i],      e1 = g_adj[i + 2];
            int e2 = g_adj[i + 4],  e3 = g_adj[i + 6];
            int e4 = g_adj[i + 8],  e5 = g_adj[i + 10];
            int e6 = g_adj[i + 12], e7 = g_adj[i + 14];
            uint2 v0 = u2[e0 * 16 + hl], v1 = u2[e1 * 16 + hl];
            uint2 v2 = u2[e2 * 16 + hl], v3 = u2[e3 * 16 + hl];
            uint2 v4 = u2[e4 * 16 + hl], v5 = u2[e5 * 16 + hl];
            uint2 v6 = u2[e6 * 16 + hl], v7 = u2[e7 * 16 + hl];
            __half2 p0x = __hadd2(*(__half2*)&v0.x, *(__half2*)&v1.x);
            __half2 p0y = __hadd2(*(__half2*)&v0.y, *(__half2*)&v1.y);
            __half2 p1x = __hadd2(*(__half2*)&v2.x, *(__half2*)&v3.x);
            __half2 p1y = __hadd2(*(__half2*)&v2.y, *(__half2*)&v3.y);
            __half2 p2x = __hadd2(*(__half2*)&v4.x, *(__half2*)&v5.x);
            __half2 p2y = __hadd2(*(__half2*)&v4.y, *(__half2*)&v5.y);
            __half2 p3x = __hadd2(*(__half2*)&v6.x, *(__half2*)&v7.x);
            __half2 p3y = __hadd2(*(__half2*)&v6.y, *(__half2*)&v7.y);
            float2 f0x = __half22float2(p0x), f0y = __half22float2(p0y);
            float2 f1x = __half22float2(p1x), f1y = __half22float2(p1y);
            float2 f2x = __half22float2(p2x), f2y = __half22float2(p2y);
            float2 f3x = __half22float2(p3x), f3y = __half22float2(p3y);
            acc.x += (f0x.x + f1x.x) + (f2x.x + f3x.x);
            acc.y += (f0x.y + f1x.y) + (f2x.y + f3x.y);
            acc.z += (f0y.x + f1y.x) + (f2y.x + f3y.x);
            acc.w += (f0y.y + f1y.y) + (f2y.y + f3y.y);
        }
        for (; i + 6 < end; i += 8) {
            int e0 = g_adj[i],     e1 = g_adj[i + 2];
            int e2 = g_adj[i + 4], e3 = g_adj[i + 6];
            uint2 v0 = u2[e0 * 16 + hl], v1 = u2[e1 * 16 + hl];
            uint2 v2 = u2[e2 * 16 + hl], v3 = u2[e3 * 16 + hl];
            __half2 p0x = __hadd2(*(__half2*)&v0.x, *(__half2*)&v1.x);
            __half2 p0y = __hadd2(*(__half2*)&v0.y, *(__half2*)&v1.y);
            __half2 p1x = __hadd2(*(__half2*)&v2.x, *(__half2*)&v3.x);
            __half2 p1y = __hadd2(*(__half2*)&v2.y, *(__half2*)&v3.y);
            float2 f0x = __half22float2(p0x), f0y = __half22float2(p0y);
            float2 f1x = __half22float2(p1x), f1y = __half22float2(p1y);
            acc.x += f0x.x + f1x.x;
            acc.y += f0x.y + f1x.y;
            acc.z += f0y.x + f1y.x;
            acc.w += f0y.y + f1y.y;
        }
        for (; i < end; i += 2) {
            int s = g_adj[i];
            uint2 v = u2[s * 16 + hl];
            float2 f0 = __half22float2(*(__half2*)&v.x);
            float2 f1 = __half22float2(*(__half2*)&v.y);
            acc.x += f0.x; acc.y += f0.y; acc.z += f1.x; acc.w += f1.y;
        }
        acc.x += __shfl_xor_sync(0xffffffffu, acc.x, 16);
        acc.y += __shfl_xor_sync(0xffffffffu, acc.y, 16);
        acc.z += __shfl_xor_sync(0xffffffffu, acc.z, 16);
        acc.w += __shfl_xor_sync(0xffffffffu, acc.w, 16);

        if (half == 0) {
            float4 o;
            o.x = fmaf(acc.x, dv, bvec.x);
            o.y = fmaf(acc.y, dv, bvec.y);
            o.z = fmaf(acc.z, dv, bvec.z);
            o.w = fmaf(acc.w, dv, bvec.w);
            ((float4*)g_agg)[(long long)n * 16 + hl] = o;
            s1.x += o.x; s1.y += o.y; s1.z += o.z; s1.w += o.w;
            s2.x = fmaf(o.x, o.x, s2.x); s2.y = fmaf(o.y, o.y, s2.y);
            s2.z = fmaf(o.z, o.z, s2.z); s2.w = fmaf(o.w, o.w, s2.w);
        }
    }

    if (half == 0) {
        atomicAdd(&ss[4 * hl + 0], s1.x); atomicAdd(&ss[4 * hl + 1], s1.y);
        atomicAdd(&ss[4 * hl + 2], s1.z); atomicAdd(&ss[4 * hl + 3], s1.w);
        atomicAdd(&sq[4 * hl + 0], s2.x); atomicAdd(&sq[4 * hl + 1], s2.y);
        atomicAdd(&sq[4 * hl + 2], s2.z); atomicAdd(&sq[4 * hl + 3], s2.w);
    }
    __syncthreads();
    if (threadIdx.x < HID) {
        atomicAdd(&g_sum3[slot * HID + threadIdx.x],   ss[threadIdx.x]);
        atomicAdd(&g_sumsq3[slot * HID + threadIdx.x], sq[threadIdx.x]);
    }
}

// ---------------- classifier + cleanup (re-zero g_cnt for next replay) -------
__global__ void k_classifier(const float* __restrict__ Wc1, const float* __restrict__ bc1,
                             const float* __restrict__ Wc2, const float* __restrict__ bc2,
                             const float* __restrict__ gamma, const float* __restrict__ beta,
                             float* __restrict__ out, int N) {
    int gid = blockIdx.x * blockDim.x + threadIdx.x;
    if (gid < N) g_cnt[gid] = 0;   // cleanup for next graph replay

    __shared__ float W1[64 * 32];
    __shared__ float W2[64];
    __shared__ float b1s[32];
    __shared__ float b2s[2];
    for (int i = threadIdx.x; i < 64 * 32; i += blockDim.x) W1[i] = Wc1[i];
    if (threadIdx.x < 64) W2[threadIdx.x] = Wc2[threadIdx.x];
    if (threadIdx.x < 32) b1s[threadIdx.x] = bc1[threadIdx.x];
    if (threadIdx.x < 2)  b2s[threadIdx.x] = bc2[threadIdx.x];
    __syncthreads();
    int lane = threadIdx.x & 31, warp = threadIdx.x >> 5;
    int n = blockIdx.x * (blockDim.x >> 5) + warp;
    if (n >= N) return;
    float inv = 1.0f / (float)N;
    int c0 = lane, c1 = lane + 32;
    float mu0 = g_sum3[2 * HID + c0] * inv;
    float mu1 = g_sum3[2 * HID + c1] * inv;
    float v0 = g_sumsq3[2 * HID + c0] * inv - mu0 * mu0;
    float v1 = g_sumsq3[2 * HID + c1] * inv - mu1 * mu1;
    float sc0 = gamma[c0] * rsqrtf(v0 + EPSV);
    float sc1 = gamma[c1] * rsqrtf(v1 + EPSV);
    float sh0 = fmaf(-mu0, sc0, beta[c0]);
    float sh1 = fmaf(-mu1, sc1, beta[c1]);

    float vlo = fmaf(g_agg[n * HID + c0], sc0, sh0);
    float vhi = fmaf(g_agg[n * HID + c1], sc1, sh1);
    float u = b1s[lane];
#pragma unroll
    for (int c = 0; c < 32; c++) {
        float xc = __shfl_sync(0xffffffffu, vlo, c);
        u = fmaf(xc, W1[c * 32 + lane], u);
    }
#pragma unroll
    for (int c = 0; c < 32; c++) {
        float xc = __shfl_sync(0xffffffffu, vhi, c);
        u = fmaf(xc, W1[(c + 32) * 32 + lane], u);
    }
    u = fmaxf(u, 0.f);
    float p0 = u * W2[lane * 2], p1 = u * W2[lane * 2 + 1];
#pragma unroll
    for (int o = 16; o > 0; o >>= 1) {
        p0 += __shfl_xor_sync(0xffffffffu, p0, o);
        p1 += __shfl_xor_sync(0xffffffffu, p1, o);
    }
    if (lane == 0) {
        out[n * 2]     = p0 + b2s[0];
        out[n * 2 + 1] = p1 + b2s[1];
    }
}

// ---------------- launch ------------------------------------------------------
extern "C" void kernel_launch(void* const* d_in, const int* in_sizes, int n_in,
                              void* d_out, int out_size) {
    const float* x    = (const float*)d_in[0];
    const void*  ei   = d_in[1];
    const float* W_in = (const float*)d_in[2];
    const float* b_in = (const float*)d_in[3];
    const float* W_g  = (const float*)d_in[4];
    const float* b_g  = (const float*)d_in[5];
    const float* gam  = (const float*)d_in[6];
    const float* bet  = (const float*)d_in[7];
    const float* W_c1 = (const float*)d_in[8];
    const float* b_c1 = (const float*)d_in[9];
    const float* W_c2 = (const float*)d_in[10];
    const float* b_c2 = (const float*)d_in[11];
    float* out = (float*)d_out;

    int N = in_sizes[0] / 12;
    long long E = (long long)in_sizes[1] / 2;

    const int TB = 256;
    unsigned nBlocks = (unsigned)((N + TB - 1) / TB);
    unsigned eBlocks = (unsigned)((E + TB - 1) / TB);
    int NB = (N + 1023) / 1024;
    int eB = (int)eBlocks;
    int gB = (N + 15) / 16;                         // layer0 blocks (2 nodes/warp)
    int half_e = (eB + 1) / 2;
    unsigned hetero = 3u * (unsigned)(half_e > gB ? half_e : gB);
    const unsigned AGG_BLOCKS = 1184;               // 148 SMs x 8 blocks: one full wave

    k_cnt<<<eBlocks, TB>>>(ei, E);                          // #1
    k_scan1<<<(unsigned)NB, 1024>>>(N);                     // #2
    k_scan23<<<nBlocks, TB>>>(N, (int)E, NB);               // #3
    k_fill_layer0<<<hetero, TB>>>(ei, E, x, W_in, b_in,
                                  W_g, N, eB, gB);          // #4 <- profiled
    k_agg<<<AGG_BLOCKS, 256>>>(b_g, 0, N);                  // #5
    for (int l = 1; l < 3; l++) {
        k_gemm64<<<(unsigned)gB, 256>>>(W_g + (long long)l * HID * HID,
                                        gam + (l - 1) * HID, bet + (l - 1) * HID,
                                        l - 1, N);
        k_agg<<<AGG_BLOCKS, 256>>>(b_g + l * HID, l, N);
    }
    k_classifier<<<(unsigned)((N + 7) / 8), 256>>>(W_c1, b_c1, W_c2, b_c2,
                                                   gam + 2 * HID, bet + 2 * HID,
                                                   out, N);
}